// round 3
// baseline (speedup 1.0000x reference)
#include <cuda_runtime.h>

#define NN 50000
#define EE 800000
#define DD 128
#define HH 4

// ---- scratch (device globals; no allocation allowed) ----
__device__ float g_K[NN * DD];
__device__ float g_M[NN * DD];
__device__ float g_Q[NN * DD];
__device__ float g_ev[EE * HH];
__device__ float g_ssum[NN * HH];
__device__ float g_cnt[NN];
__device__ float g_rnorm[NN * HH];
__device__ float g_out[NN * DD];
__device__ float g_h[NN * DD];
__device__ float g_colsum[DD];
__device__ float g_colsumsq[DD];
__device__ float g_scale[DD];
__device__ float g_shift[DD];
__device__ int   g_src[EE];
__device__ int   g_dst[EE];
__device__ int   g_is64;

#define ASTRIDE 132   // padded to break 16-way STS conflicts on A transpose

// =======================================================================
// edge_index dtype probe: reference asks for int64 but JAX x64-disabled
// silently yields int32. Interpret first 2048 entries as u64; all < NN
// only if genuinely int64 (int32 data gives lo + hi*2^32 with random hi).
// =======================================================================
__global__ void k_detect(const unsigned long long* __restrict__ p)
{
    if (blockIdx.x == 0 && threadIdx.x == 0) {
        int ok = 1;
        for (int i = 0; i < 2048; i++) {
            if (p[i] >= (unsigned long long)NN) { ok = 0; break; }
        }
        g_is64 = ok;
    }
}

// materialize int32 src/dst once
__global__ void k_convert(const void* __restrict__ raw)
{
    const long long* e64 = (const long long*)raw;
    const int*       e32 = (const int*)raw;
    const int is64 = g_is64;
    int i = blockIdx.x * blockDim.x + threadIdx.x;
    int stride = gridDim.x * blockDim.x;
    for (int e = i; e < EE; e += stride) {
        if (is64) { g_src[e] = (int)e64[e]; g_dst[e] = (int)e64[EE + e]; }
        else      { g_src[e] = e32[e];      g_dst[e] = e32[EE + e]; }
    }
}

// =======================================================================
// fp32 GEMM: C[rows,128] = op(A)[rows,128] @ W[128,128] + bias, * outScale
// Block: 256 threads, 128x128 output tile, 8x8 microtile, BK=64.
// BN=true applies per-column scale/shift + ReLU to A during load (fused BN).
// =======================================================================
template <bool BN>
__device__ __forceinline__ void gemm_body(
    const float* __restrict__ A, const float* __restrict__ W,
    const float* __restrict__ bias, float* __restrict__ C, float outScale)
{
    extern __shared__ float smem[];
    float* As = smem;                 // [64][ASTRIDE]  (As[k][row])
    float* Ws = smem + 64 * ASTRIDE;  // [64][128]
    const int tid = threadIdx.x;
    const int rowBase = blockIdx.x * 128;
    const int tx = tid & 15;
    const int ty = tid >> 4;

    float acc[8][8];
#pragma unroll
    for (int i = 0; i < 8; i++)
#pragma unroll
        for (int j = 0; j < 8; j++) acc[i][j] = 0.f;

    for (int kc = 0; kc < DD; kc += 64) {
        // load + transpose A tile (zero-pad OOB rows)
#pragma unroll
        for (int it = 0; it < 8; it++) {
            int idx = tid + it * 256;       // 0..2047
            int r   = idx >> 4;             // 0..127
            int c4  = idx & 15;             // 0..15
            int grow = rowBase + r;
            float4 v = make_float4(0.f, 0.f, 0.f, 0.f);
            if (grow < NN) v = *(const float4*)(A + (size_t)grow * DD + kc + c4 * 4);
            if (BN) {
                int cb = kc + c4 * 4;
                v.x = fmaxf(v.x * g_scale[cb + 0] + g_shift[cb + 0], 0.f);
                v.y = fmaxf(v.y * g_scale[cb + 1] + g_shift[cb + 1], 0.f);
                v.z = fmaxf(v.z * g_scale[cb + 2] + g_shift[cb + 2], 0.f);
                v.w = fmaxf(v.w * g_scale[cb + 3] + g_shift[cb + 3], 0.f);
            }
            As[(c4 * 4 + 0) * ASTRIDE + r] = v.x;
            As[(c4 * 4 + 1) * ASTRIDE + r] = v.y;
            As[(c4 * 4 + 2) * ASTRIDE + r] = v.z;
            As[(c4 * 4 + 3) * ASTRIDE + r] = v.w;
        }
        // load W tile
#pragma unroll
        for (int it = 0; it < 8; it++) {
            int idx = tid + it * 256;
            int k  = idx >> 5;              // 0..63
            int c4 = idx & 31;              // 0..31
            *(float4*)(Ws + k * 128 + c4 * 4) =
                *(const float4*)(W + (size_t)(kc + k) * DD + c4 * 4);
        }
        __syncthreads();

#pragma unroll 16
        for (int k = 0; k < 64; k++) {
            float av[8], bv[8];
            *(float4*)&av[0] = *(const float4*)(As + k * ASTRIDE + ty * 8);
            *(float4*)&av[4] = *(const float4*)(As + k * ASTRIDE + ty * 8 + 4);
            *(float4*)&bv[0] = *(const float4*)(Ws + k * 128 + tx * 8);
            *(float4*)&bv[4] = *(const float4*)(Ws + k * 128 + tx * 8 + 4);
#pragma unroll
            for (int i = 0; i < 8; i++)
#pragma unroll
                for (int j = 0; j < 8; j++)
                    acc[i][j] = fmaf(av[i], bv[j], acc[i][j]);
        }
        __syncthreads();
    }

    float bvv[8];
#pragma unroll
    for (int j = 0; j < 8; j++) bvv[j] = bias[tx * 8 + j];
#pragma unroll
    for (int i = 0; i < 8; i++) {
        int grow = rowBase + ty * 8 + i;
        if (grow < NN) {
            float o[8];
#pragma unroll
            for (int j = 0; j < 8; j++) o[j] = (acc[i][j] + bvv[j]) * outScale;
            *(float4*)(C + (size_t)grow * DD + tx * 8)     = *(float4*)&o[0];
            *(float4*)(C + (size_t)grow * DD + tx * 8 + 4) = *(float4*)&o[4];
        }
    }
}

// 3 projection GEMMs in one launch (grid.y selects K/M/Q)
__global__ void __launch_bounds__(256, 2) k_gemm_proj(
    const float* __restrict__ x,
    const float* __restrict__ Wk, const float* __restrict__ bk,
    const float* __restrict__ Wm, const float* __restrict__ bm,
    const float* __restrict__ Wq, const float* __restrict__ bq)
{
    const float* W; const float* b; float* C; float sc = 1.f;
    if (blockIdx.y == 0)      { W = Wk; b = bk; C = g_K; }
    else if (blockIdx.y == 1) { W = Wm; b = bm; C = g_M; }
    else                      { W = Wq; b = bq; C = g_Q; sc = 0.17677669529663687f; } // 1/sqrt(32)
    gemm_body<false>(x, W, b, C, sc);
}

__global__ void __launch_bounds__(256, 2) k_gemm_mlp1(
    const float* __restrict__ W1, const float* __restrict__ b1)
{
    gemm_body<false>(g_out, W1, b1, g_h, 1.f);
}

__global__ void __launch_bounds__(256, 2) k_gemm_mlp2(
    const float* __restrict__ W2, const float* __restrict__ b2,
    float* __restrict__ outp)
{
    gemm_body<true>(g_h, W2, b2, outp, 1.f);
}

// =======================================================================
// init: zero accumulators
// =======================================================================
__global__ void k_init()
{
    int i = blockIdx.x * blockDim.x + threadIdx.x;
    int stride = gridDim.x * blockDim.x;
    for (int j = i; j < NN * DD; j += stride) g_out[j] = 0.f;
    for (int j = i; j < NN * HH; j += stride) g_ssum[j] = 0.f;
    for (int j = i; j < NN; j += stride) g_cnt[j] = 0.f;
    if (i < DD) { g_colsum[i] = 0.f; g_colsumsq[i] = 0.f; }
}

// =======================================================================
// edge pass 1: scores -> exp, segment-sum over src, edge count per src
// warp per edge; lane l owns dims [4l,4l+4); head = l>>3
// =======================================================================
__global__ void __launch_bounds__(256) k_edge_scores()
{
    int gwarp  = (blockIdx.x * blockDim.x + threadIdx.x) >> 5;
    int nwarps = (gridDim.x * blockDim.x) >> 5;
    int lane   = threadIdx.x & 31;
    for (int e = gwarp; e < EE; e += nwarps) {
        int src = g_src[e];
        int dst = g_dst[e];
        float4 q = *(const float4*)(g_Q + (size_t)src * DD + lane * 4);
        float4 k = *(const float4*)(g_K + (size_t)dst * DD + lane * 4);
        float p = q.x * k.x + q.y * k.y + q.z * k.z + q.w * k.w;
        p += __shfl_xor_sync(0xffffffffu, p, 1);
        p += __shfl_xor_sync(0xffffffffu, p, 2);
        p += __shfl_xor_sync(0xffffffffu, p, 4);
        // softmax without max-subtraction: scores are O(1), exp is safe and
        // alpha = e/sum is mathematically identical to the max-shifted form.
        float ev = __expf(p);
        if ((lane & 7) == 0) {
            int h = lane >> 3;
            g_ev[(size_t)e * HH + h] = ev;
            atomicAdd(&g_ssum[src * HH + h], ev);
        }
        if (lane == 0) atomicAdd(&g_cnt[src], 1.0f);
    }
}

// per-(node,head) normalizer: cnt[src] / ssum[src,h]
__global__ void k_rnorm()
{
    int i = blockIdx.x * blockDim.x + threadIdx.x;
    if (i < NN * HH) {
        float s = g_ssum[i];
        float c = g_cnt[i >> 2];
        g_rnorm[i] = (s > 0.f) ? (c / s) : 0.f;
    }
}

// =======================================================================
// edge pass 2: out[dst] += M[src] * alpha  (scatter atomics)
// =======================================================================
__global__ void __launch_bounds__(256) k_aggregate()
{
    int gwarp  = (blockIdx.x * blockDim.x + threadIdx.x) >> 5;
    int nwarps = (gridDim.x * blockDim.x) >> 5;
    int lane   = threadIdx.x & 31;
    int h      = lane >> 3;
    for (int e = gwarp; e < EE; e += nwarps) {
        int src = g_src[e];
        int dst = g_dst[e];
        float alpha = g_ev[(size_t)e * HH + h] * g_rnorm[src * HH + h];
        float4 m = *(const float4*)(g_M + (size_t)src * DD + lane * 4);
        float* o = g_out + (size_t)dst * DD + lane * 4;
        atomicAdd(o + 0, m.x * alpha);
        atomicAdd(o + 1, m.y * alpha);
        atomicAdd(o + 2, m.z * alpha);
        atomicAdd(o + 3, m.w * alpha);
    }
}

// =======================================================================
// BN stats over columns of g_h (training-mode batch stats, biased var)
// =======================================================================
__global__ void __launch_bounds__(128) k_colstats()
{
    int col = threadIdx.x;  // 0..127
    float s = 0.f, s2 = 0.f;
    for (int r = blockIdx.x; r < NN; r += gridDim.x) {
        float v = g_h[(size_t)r * DD + col];
        s += v; s2 += v * v;
    }
    atomicAdd(&g_colsum[col], s);
    atomicAdd(&g_colsumsq[col], s2);
}

__global__ void k_bnfinal(const float* __restrict__ gamma, const float* __restrict__ beta)
{
    int c = threadIdx.x;
    float invN = 1.0f / (float)NN;
    float mean = g_colsum[c] * invN;
    float var  = g_colsumsq[c] * invN - mean * mean;
    float rstd = rsqrtf(var + 1e-5f);
    float sc = rstd * gamma[c];
    g_scale[c] = sc;
    g_shift[c] = beta[c] - mean * sc;
}

// =======================================================================
// launcher
// =======================================================================
extern "C" void kernel_launch(void* const* d_in, const int* in_sizes, int n_in,
                              void* d_out, int out_size)
{
    const float* x     = (const float*)d_in[0];
    const void*  ei    = d_in[1];   // int32 or int64, probed on device
    const float* Wk    = (const float*)d_in[2];
    const float* bk    = (const float*)d_in[3];
    const float* Wm    = (const float*)d_in[4];
    const float* bm    = (const float*)d_in[5];
    const float* Wq    = (const float*)d_in[6];
    const float* bq    = (const float*)d_in[7];
    const float* W1    = (const float*)d_in[8];
    const float* b1    = (const float*)d_in[9];
    const float* gamma = (const float*)d_in[10];
    const float* beta  = (const float*)d_in[11];
    const float* W2    = (const float*)d_in[12];
    const float* b2    = (const float*)d_in[13];
    float* out = (float*)d_out;

    const int GEMM_SMEM = (64 * ASTRIDE + 64 * 128) * 4;  // 66560 B
    cudaFuncSetAttribute(k_gemm_proj, cudaFuncAttributeMaxDynamicSharedMemorySize, GEMM_SMEM);
    cudaFuncSetAttribute(k_gemm_mlp1, cudaFuncAttributeMaxDynamicSharedMemorySize, GEMM_SMEM);
    cudaFuncSetAttribute(k_gemm_mlp2, cudaFuncAttributeMaxDynamicSharedMemorySize, GEMM_SMEM);

    const int rowTiles = (NN + 127) / 128;  // 391

    k_detect<<<1, 32>>>((const unsigned long long*)ei);
    k_convert<<<512, 256>>>(ei);
    k_init<<<256, 256>>>();
    k_gemm_proj<<<dim3(rowTiles, 3), 256, GEMM_SMEM>>>(x, Wk, bk, Wm, bm, Wq, bq);
    k_edge_scores<<<4096, 256>>>();
    k_rnorm<<<(NN * HH + 255) / 256, 256>>>();
    k_aggregate<<<4096, 256>>>();
    k_gemm_mlp1<<<rowTiles, 256, GEMM_SMEM>>>(W1, b1);
    k_colstats<<<512, 128>>>();
    k_bnfinal<<<1, 128>>>(gamma, beta);
    k_gemm_mlp2<<<rowTiles, 256, GEMM_SMEM>>>(W2, b2, out);
}

// round 4
// speedup vs baseline: 1.1502x; 1.1502x over previous
#include <cuda_runtime.h>

#define NN 50000
#define EE 800000
#define DD 128
#define HH 4

// ---- scratch (device globals; no allocation allowed) ----
__device__ float g_K[NN * DD];
__device__ float g_M[NN * DD];
__device__ float g_Q[NN * DD];
__device__ float g_ev[EE * HH];
__device__ float g_rnorm[NN * HH];
__device__ float g_out[NN * DD];
__device__ float g_h[NN * DD];
__device__ float g_colsum[DD];
__device__ float g_colsumsq[DD];
__device__ float g_scale[DD];
__device__ float g_shift[DD];
__device__ int   g_is64;

// CSR structures (by src and by dst)
__device__ int g_deg_s[NN];
__device__ int g_deg_d[NN];
__device__ int g_off_s[NN + 1];
__device__ int g_off_d[NN + 1];
__device__ int g_cur_s[NN];
__device__ int g_cur_d[NN];
__device__ int g_csr_s_dst[EE];
__device__ int g_csr_s_eid[EE];
__device__ int g_csr_d_src[EE];
__device__ int g_csr_d_eid[EE];

#define ASTRIDE 132   // padded to break 16-way STS conflicts on A transpose

// =======================================================================
// edge_index dtype probe: reference asks int64 but JAX x64-disabled yields
// int32. All-first-2048-u64 < NN only if genuinely int64.
// =======================================================================
__global__ void k_detect(const unsigned long long* __restrict__ p)
{
    if (threadIdx.x == 0) {
        int ok = 1;
        for (int i = 0; i < 2048; i++)
            if (p[i] >= (unsigned long long)NN) { ok = 0; break; }
        g_is64 = ok;
    }
}

// zero the small accumulators + degree histograms
__global__ void k_init()
{
    int i = blockIdx.x * blockDim.x + threadIdx.x;
    int stride = gridDim.x * blockDim.x;
    for (int j = i; j < NN; j += stride) { g_deg_s[j] = 0; g_deg_d[j] = 0; }
    if (i < DD) { g_colsum[i] = 0.f; g_colsumsq[i] = 0.f; }
}

// materialize int32 src/dst once + degree histograms
__global__ void k_convert(const void* __restrict__ raw,
                          int* __restrict__ srcA, int* __restrict__ dstA)
{
    const long long* e64 = (const long long*)raw;
    const int*       e32 = (const int*)raw;
    const int is64 = g_is64;
    int i = blockIdx.x * blockDim.x + threadIdx.x;
    int stride = gridDim.x * blockDim.x;
    for (int e = i; e < EE; e += stride) {
        int s, d;
        if (is64) { s = (int)e64[e]; d = (int)e64[EE + e]; }
        else      { s = e32[e];      d = e32[EE + e]; }
        srcA[e] = s; dstA[e] = d;
        atomicAdd(&g_deg_s[s], 1);
        atomicAdd(&g_deg_d[d], 1);
    }
}

// exclusive scan of degree arrays (one block per array)
__global__ void __launch_bounds__(1024) k_scan()
{
    const int* deg = blockIdx.x ? g_deg_d : g_deg_s;
    int* off = blockIdx.x ? g_off_d : g_off_s;
    int* cur = blockIdx.x ? g_cur_d : g_cur_s;
    __shared__ int partial[1024];
    const int t = threadIdx.x;
    const int chunk = (NN + 1023) / 1024;  // 49
    int base = t * chunk;
    int lim = NN - base; if (lim < 0) lim = 0; if (lim > chunk) lim = chunk;
    int s = 0;
    for (int i = 0; i < lim; i++) s += deg[base + i];
    partial[t] = s;
    __syncthreads();
    for (int d = 1; d < 1024; d <<= 1) {
        int v = 0;
        if (t >= d) v = partial[t - d];
        __syncthreads();
        if (t >= d) partial[t] += v;
        __syncthreads();
    }
    int run = partial[t] - s;  // exclusive
    for (int i = 0; i < lim; i++) {
        off[base + i] = run;
        cur[base + i] = run;
        run += deg[base + i];
    }
    if (t == 1023) off[NN] = run;
}

// scatter edge ids into both CSRs
__global__ void k_scatter(const int* __restrict__ srcA, const int* __restrict__ dstA)
{
    int i = blockIdx.x * blockDim.x + threadIdx.x;
    int stride = gridDim.x * blockDim.x;
    for (int e = i; e < EE; e += stride) {
        int s = srcA[e], d = dstA[e];
        int ps = atomicAdd(&g_cur_s[s], 1);
        g_csr_s_dst[ps] = d;
        g_csr_s_eid[ps] = e;
        int pd = atomicAdd(&g_cur_d[d], 1);
        g_csr_d_src[pd] = s;
        g_csr_d_eid[pd] = e;
    }
}

// =======================================================================
// fp32 GEMM: C[rows,128] = op(A)[rows,128] @ W[128,128] + bias, * outScale
// BN=true: per-column scale/shift + ReLU applied to A on load (fused BN).
// STATS=true: accumulate per-column sum/sumsq of the OUTPUT (for BN stats).
// =======================================================================
template <bool BN, bool STATS>
__device__ __forceinline__ void gemm_body(
    const float* __restrict__ A, const float* __restrict__ W,
    const float* __restrict__ bias, float* __restrict__ C, float outScale)
{
    extern __shared__ float smem[];
    float* As = smem;                 // [64][ASTRIDE]
    float* Ws = smem + 64 * ASTRIDE;  // [64][128]
    const int tid = threadIdx.x;
    const int rowBase = blockIdx.x * 128;
    const int tx = tid & 15;
    const int ty = tid >> 4;

    float acc[8][8];
#pragma unroll
    for (int i = 0; i < 8; i++)
#pragma unroll
        for (int j = 0; j < 8; j++) acc[i][j] = 0.f;

    for (int kc = 0; kc < DD; kc += 64) {
#pragma unroll
        for (int it = 0; it < 8; it++) {
            int idx = tid + it * 256;
            int r   = idx >> 4;
            int c4  = idx & 15;
            int grow = rowBase + r;
            float4 v = make_float4(0.f, 0.f, 0.f, 0.f);
            if (grow < NN) v = *(const float4*)(A + (size_t)grow * DD + kc + c4 * 4);
            if (BN) {
                int cb = kc + c4 * 4;
                v.x = fmaxf(v.x * g_scale[cb + 0] + g_shift[cb + 0], 0.f);
                v.y = fmaxf(v.y * g_scale[cb + 1] + g_shift[cb + 1], 0.f);
                v.z = fmaxf(v.z * g_scale[cb + 2] + g_shift[cb + 2], 0.f);
                v.w = fmaxf(v.w * g_scale[cb + 3] + g_shift[cb + 3], 0.f);
            }
            As[(c4 * 4 + 0) * ASTRIDE + r] = v.x;
            As[(c4 * 4 + 1) * ASTRIDE + r] = v.y;
            As[(c4 * 4 + 2) * ASTRIDE + r] = v.z;
            As[(c4 * 4 + 3) * ASTRIDE + r] = v.w;
        }
#pragma unroll
        for (int it = 0; it < 8; it++) {
            int idx = tid + it * 256;
            int k  = idx >> 5;
            int c4 = idx & 31;
            *(float4*)(Ws + k * 128 + c4 * 4) =
                *(const float4*)(W + (size_t)(kc + k) * DD + c4 * 4);
        }
        __syncthreads();

#pragma unroll 16
        for (int k = 0; k < 64; k++) {
            float av[8], bv[8];
            *(float4*)&av[0] = *(const float4*)(As + k * ASTRIDE + ty * 8);
            *(float4*)&av[4] = *(const float4*)(As + k * ASTRIDE + ty * 8 + 4);
            *(float4*)&bv[0] = *(const float4*)(Ws + k * 128 + tx * 8);
            *(float4*)&bv[4] = *(const float4*)(Ws + k * 128 + tx * 8 + 4);
#pragma unroll
            for (int i = 0; i < 8; i++)
#pragma unroll
                for (int j = 0; j < 8; j++)
                    acc[i][j] = fmaf(av[i], bv[j], acc[i][j]);
        }
        __syncthreads();
    }

    float bvv[8];
#pragma unroll
    for (int j = 0; j < 8; j++) bvv[j] = bias[tx * 8 + j];

    float s1[8], s2[8];
    if (STATS) {
#pragma unroll
        for (int j = 0; j < 8; j++) { s1[j] = 0.f; s2[j] = 0.f; }
    }

#pragma unroll
    for (int i = 0; i < 8; i++) {
        int grow = rowBase + ty * 8 + i;
        if (grow < NN) {
            float o[8];
#pragma unroll
            for (int j = 0; j < 8; j++) {
                o[j] = (acc[i][j] + bvv[j]) * outScale;
                if (STATS) { s1[j] += o[j]; s2[j] += o[j] * o[j]; }
            }
            *(float4*)(C + (size_t)grow * DD + tx * 8)     = *(float4*)&o[0];
            *(float4*)(C + (size_t)grow * DD + tx * 8 + 4) = *(float4*)&o[4];
        }
    }

    if (STATS) {
        // reduce per-column partials across the 16 ty-groups via smem
        float2* red = (float2*)smem;   // [16][128] float2 = 16KB, smem reusable here
        __syncthreads();
#pragma unroll
        for (int j = 0; j < 8; j++)
            red[ty * 128 + tx * 8 + j] = make_float2(s1[j], s2[j]);
        __syncthreads();
        if (tid < 128) {
            float a = 0.f, b = 0.f;
#pragma unroll
            for (int r = 0; r < 16; r++) {
                float2 v = red[r * 128 + tid];
                a += v.x; b += v.y;
            }
            atomicAdd(&g_colsum[tid], a);
            atomicAdd(&g_colsumsq[tid], b);
        }
    }
}

// 3 projection GEMMs in one launch (grid.y selects K/M/Q)
__global__ void __launch_bounds__(256, 2) k_gemm_proj(
    const float* __restrict__ x,
    const float* __restrict__ Wk, const float* __restrict__ bk,
    const float* __restrict__ Wm, const float* __restrict__ bm,
    const float* __restrict__ Wq, const float* __restrict__ bq)
{
    const float* W; const float* b; float* C; float sc = 1.f;
    if (blockIdx.y == 0)      { W = Wk; b = bk; C = g_K; }
    else if (blockIdx.y == 1) { W = Wm; b = bm; C = g_M; }
    else                      { W = Wq; b = bq; C = g_Q; sc = 0.17677669529663687f; } // 1/sqrt(32)
    gemm_body<false, false>(x, W, b, C, sc);
}

__global__ void __launch_bounds__(256, 2) k_gemm_mlp1(
    const float* __restrict__ W1, const float* __restrict__ b1)
{
    gemm_body<false, true>(g_out, W1, b1, g_h, 1.f);
}

__global__ void __launch_bounds__(256, 2) k_gemm_mlp2(
    const float* __restrict__ W2, const float* __restrict__ b2,
    float* __restrict__ outp)
{
    gemm_body<true, false>(g_h, W2, b2, outp, 1.f);
}

// =======================================================================
// pass 1 (CSR by src): warp per src node. Q[src] cached in registers,
// gather K[dst] per edge, softmax denominators in registers. No atomics.
// =======================================================================
__global__ void __launch_bounds__(256) k_edge_scores()
{
    int gwarp  = (blockIdx.x * blockDim.x + threadIdx.x) >> 5;
    int nwarps = (gridDim.x * blockDim.x) >> 5;
    int lane   = threadIdx.x & 31;
    for (int n = gwarp; n < NN; n += nwarps) {
        int beg = g_off_s[n];
        int end = g_off_s[n + 1];
        if (beg == end) continue;
        float4 q = *(const float4*)(g_Q + (size_t)n * DD + lane * 4);
        float ls = 0.f;  // local softmax sum (valid on octet leaders)
#pragma unroll 2
        for (int e = beg; e < end; e++) {
            int dst = g_csr_s_dst[e];
            float4 k = *(const float4*)(g_K + (size_t)dst * DD + lane * 4);
            float p = q.x * k.x + q.y * k.y + q.z * k.z + q.w * k.w;
            p += __shfl_xor_sync(0xffffffffu, p, 1);
            p += __shfl_xor_sync(0xffffffffu, p, 2);
            p += __shfl_xor_sync(0xffffffffu, p, 4);
            // softmax without max-shift: scores O(1), exp safe; alpha identical.
            float ev = __expf(p);
            if ((lane & 7) == 0) {
                int eid = g_csr_s_eid[e];
                g_ev[(size_t)eid * HH + (lane >> 3)] = ev;
                ls += ev;
            }
        }
        if ((lane & 7) == 0) {
            float deg = (float)(end - beg);
            g_rnorm[n * HH + (lane >> 3)] = deg / ls;
        }
    }
}

// =======================================================================
// pass 2 (CSR by dst): warp per dst node; accumulate alpha*M[src] in
// registers, single coalesced store. No atomics, no g_out init needed.
// =======================================================================
__global__ void __launch_bounds__(256) k_aggregate()
{
    int gwarp  = (blockIdx.x * blockDim.x + threadIdx.x) >> 5;
    int nwarps = (gridDim.x * blockDim.x) >> 5;
    int lane   = threadIdx.x & 31;
    int h      = lane >> 3;
    for (int n = gwarp; n < NN; n += nwarps) {
        int beg = g_off_d[n];
        int end = g_off_d[n + 1];
        float4 acc = make_float4(0.f, 0.f, 0.f, 0.f);
#pragma unroll 2
        for (int e = beg; e < end; e++) {
            int src = g_csr_d_src[e];
            int eid = g_csr_d_eid[e];
            float alpha = g_ev[(size_t)eid * HH + h] * g_rnorm[src * HH + h];
            float4 m = *(const float4*)(g_M + (size_t)src * DD + lane * 4);
            acc.x += m.x * alpha;
            acc.y += m.y * alpha;
            acc.z += m.z * alpha;
            acc.w += m.w * alpha;
        }
        *(float4*)(g_out + (size_t)n * DD + lane * 4) = acc;
    }
}

__global__ void k_bnfinal(const float* __restrict__ gamma, const float* __restrict__ beta)
{
    int c = threadIdx.x;
    float invN = 1.0f / (float)NN;
    float mean = g_colsum[c] * invN;
    float var  = g_colsumsq[c] * invN - mean * mean;
    float rstd = rsqrtf(var + 1e-5f);
    float sc = rstd * gamma[c];
    g_scale[c] = sc;
    g_shift[c] = beta[c] - mean * sc;
}

// =======================================================================
// launcher
// =======================================================================
extern "C" void kernel_launch(void* const* d_in, const int* in_sizes, int n_in,
                              void* d_out, int out_size)
{
    const float* x     = (const float*)d_in[0];
    const void*  ei    = d_in[1];   // int32 or int64, probed on device
    const float* Wk    = (const float*)d_in[2];
    const float* bk    = (const float*)d_in[3];
    const float* Wm    = (const float*)d_in[4];
    const float* bm    = (const float*)d_in[5];
    const float* Wq    = (const float*)d_in[6];
    const float* bq    = (const float*)d_in[7];
    const float* W1    = (const float*)d_in[8];
    const float* b1    = (const float*)d_in[9];
    const float* gamma = (const float*)d_in[10];
    const float* beta  = (const float*)d_in[11];
    const float* W2    = (const float*)d_in[12];
    const float* b2    = (const float*)d_in[13];
    float* out = (float*)d_out;

    // reuse csr eid arrays as temporary src/dst storage? no — need both; use
    // dedicated temp: g_csr_s_dst/g_csr_d_src are written later, safe to use
    // as the convert outputs? They'd be overwritten by scatter while still
    // being read. Use separate arrays: reuse g_ev (3.2M floats) as 2x int
    // scratch for src/dst (800k ints each) — g_ev written only in pass1,
    // after scatter is done.
    int* srcTmp = (int*)g_ev;            // 800k ints
    int* dstTmp = ((int*)g_ev) + EE;     // 800k ints

    const int GEMM_SMEM = (64 * ASTRIDE + 64 * 128) * 4;  // 66560 B
    cudaFuncSetAttribute(k_gemm_proj, cudaFuncAttributeMaxDynamicSharedMemorySize, GEMM_SMEM);
    cudaFuncSetAttribute(k_gemm_mlp1, cudaFuncAttributeMaxDynamicSharedMemorySize, GEMM_SMEM);
    cudaFuncSetAttribute(k_gemm_mlp2, cudaFuncAttributeMaxDynamicSharedMemorySize, GEMM_SMEM);

    const int rowTiles = (NN + 127) / 128;  // 391

    k_detect<<<1, 32>>>((const unsigned long long*)ei);
    k_init<<<128, 256>>>();
    k_convert<<<512, 256>>>(ei, srcTmp, dstTmp);
    k_scan<<<2, 1024>>>();
    k_scatter<<<512, 256>>>(srcTmp, dstTmp);
    k_gemm_proj<<<dim3(rowTiles, 3), 256, GEMM_SMEM>>>(x, Wk, bk, Wm, bm, Wq, bq);
    k_edge_scores<<<2048, 256>>>();
    k_aggregate<<<2048, 256>>>();
    k_gemm_mlp1<<<rowTiles, 256, GEMM_SMEM>>>(W1, b1);
    k_bnfinal<<<1, 128>>>(gamma, beta);
    k_gemm_mlp2<<<rowTiles, 256, GEMM_SMEM>>>(W2, b2, out);
}

// round 5
// speedup vs baseline: 1.9592x; 1.7034x over previous
#include <cuda_runtime.h>
#include <cstdint>

#define NN 50000
#define EE 800000
#define DD 128
#define HH 4
#define NB 49          // scan blocks per array: 49*1024 >= NN

// ---- scratch (device globals; no allocation allowed) ----
__device__ float g_K[NN * DD];
__device__ float g_M[NN * DD];
__device__ float g_Q[NN * DD];
__device__ float g_ev[EE * HH];
__device__ float g_rnorm[NN * HH];
__device__ float g_out[NN * DD];
__device__ float g_h[NN * DD];
__device__ float g_colsum[DD];
__device__ float g_colsumsq[DD];
__device__ float g_scale[DD];
__device__ float g_shift[DD];
__device__ int   g_is64;

// CSR structures (by src and by dst)
__device__ int g_deg_s[NN];
__device__ int g_deg_d[NN];
__device__ int g_off_s[NN + 1];
__device__ int g_off_d[NN + 1];
__device__ int g_cur_s[NN];     // also reused as inclusive-scan temp
__device__ int g_cur_d[NN];
__device__ int g_bsum[2][64];
__device__ int g_csr_s_dst[EE];
__device__ int g_csr_s_eid[EE];
__device__ int g_csr_d_src[EE];
__device__ int g_csr_d_eid[EE];

// =======================================================================
// edge_index dtype probe (parallel): int64 per reference, but JAX with
// x64 disabled silently yields int32. All-first-16384-u64 < NN only if
// genuinely int64.
// =======================================================================
__global__ void k_detect(const unsigned long long* __restrict__ p)
{
    __shared__ int ok;
    if (threadIdx.x == 0) ok = 1;
    __syncthreads();
    bool bad = false;
#pragma unroll
    for (int j = 0; j < 8; j++)
        if (p[threadIdx.x * 8 + j] >= (unsigned long long)NN) bad = true;
    if (bad) atomicExch(&ok, 0);
    __syncthreads();
    if (threadIdx.x == 0) g_is64 = ok;
}

__global__ void k_init()
{
    int i = blockIdx.x * blockDim.x + threadIdx.x;
    int stride = gridDim.x * blockDim.x;
    for (int j = i; j < NN; j += stride) { g_deg_s[j] = 0; g_deg_d[j] = 0; }
    if (i < DD) { g_colsum[i] = 0.f; g_colsumsq[i] = 0.f; }
}

// materialize int32 src/dst once + degree histograms
__global__ void k_convert(const void* __restrict__ raw,
                          int* __restrict__ srcA, int* __restrict__ dstA)
{
    const long long* e64 = (const long long*)raw;
    const int*       e32 = (const int*)raw;
    const int is64 = g_is64;
    int i = blockIdx.x * blockDim.x + threadIdx.x;
    int stride = gridDim.x * blockDim.x;
    for (int e = i; e < EE; e += stride) {
        int s, d;
        if (is64) { s = (int)e64[e]; d = (int)e64[EE + e]; }
        else      { s = e32[e];      d = e32[EE + e]; }
        srcA[e] = s; dstA[e] = d;
        atomicAdd(&g_deg_s[s], 1);
        atomicAdd(&g_deg_d[d], 1);
    }
}

// ---- 3-phase chip-wide exclusive scan of both degree arrays ----
__global__ void __launch_bounds__(1024) k_scanA()
{
    const int a = blockIdx.y;
    const int* deg = a ? g_deg_d : g_deg_s;
    int* tmp = a ? g_cur_d : g_cur_s;     // inclusive scan temp
    __shared__ int s[1024];
    int t = threadIdx.x;
    int i = blockIdx.x * 1024 + t;
    int v = (i < NN) ? deg[i] : 0;
    s[t] = v;
    __syncthreads();
#pragma unroll
    for (int d = 1; d < 1024; d <<= 1) {
        int u = (t >= d) ? s[t - d] : 0;
        __syncthreads();
        s[t] += u;
        __syncthreads();
    }
    if (i < NN) tmp[i] = s[t];
    if (t == 1023) g_bsum[a][blockIdx.x] = s[t];
}

__global__ void k_scanB()
{
    __shared__ int s[128];
    int t = threadIdx.x;        // 0..127
    int a = t >> 6, j = t & 63;
    int v = (j < NB) ? g_bsum[a][j] : 0;
    s[t] = v;
    __syncthreads();
#pragma unroll
    for (int d = 1; d < 64; d <<= 1) {
        int u = (j >= d) ? s[t - d] : 0;
        __syncthreads();
        s[t] += u;
        __syncthreads();
    }
    if (j < NB) g_bsum[a][j] = s[t] - v;   // exclusive base
}

__global__ void __launch_bounds__(1024) k_scanC()
{
    const int a = blockIdx.y;
    const int* deg = a ? g_deg_d : g_deg_s;
    int* tmp = a ? g_cur_d : g_cur_s;
    int* off = a ? g_off_d : g_off_s;
    int* cur = a ? g_cur_d : g_cur_s;
    int i = blockIdx.x * 1024 + threadIdx.x;
    if (i < NN) {
        int excl = tmp[i] - deg[i] + g_bsum[a][blockIdx.x];
        off[i] = excl;
        cur[i] = excl;
    }
    if (i == 0) off[NN] = EE;
}

// scatter edge ids into both CSRs
__global__ void k_scatter(const int* __restrict__ srcA, const int* __restrict__ dstA)
{
    int i = blockIdx.x * blockDim.x + threadIdx.x;
    int stride = gridDim.x * blockDim.x;
    for (int e = i; e < EE; e += stride) {
        int s = srcA[e], d = dstA[e];
        int ps = atomicAdd(&g_cur_s[s], 1);
        g_csr_s_dst[ps] = d;
        g_csr_s_eid[ps] = e;
        int pd = atomicAdd(&g_cur_d[d], 1);
        g_csr_d_src[pd] = s;
        g_csr_d_eid[pd] = e;
    }
}

// =======================================================================
// tf32 tensor-core GEMM: C[rows,128] = op(A)[rows,128] @ W[128,128] + b
// Block 256 thr = 8 warps (4x2), tile 128x128, mma.m16n8k8 tf32.
// A smem stride 36  -> compute-load bank = 4g+q  (conflict-free)
// W smem stride 136 -> compute-load bank = 8q+g  (conflict-free)
// BN=true: per-column scale/shift + ReLU applied to A on load.
// =======================================================================
#define AS_STRIDE 36
#define WS_STRIDE 136

__device__ __forceinline__ uint32_t f2tf(float x)
{
    uint32_t r;
    asm("cvt.rna.tf32.f32 %0, %1;" : "=r"(r) : "f"(x));
    return r;
}

__device__ __forceinline__ void mma_tf32(float* c, const uint32_t* a, const uint32_t* b)
{
    asm volatile(
        "mma.sync.aligned.m16n8k8.row.col.f32.tf32.tf32.f32 "
        "{%0,%1,%2,%3}, {%4,%5,%6,%7}, {%8,%9}, {%0,%1,%2,%3};"
        : "+f"(c[0]), "+f"(c[1]), "+f"(c[2]), "+f"(c[3])
        : "r"(a[0]), "r"(a[1]), "r"(a[2]), "r"(a[3]), "r"(b[0]), "r"(b[1]));
}

template <bool BN>
__device__ __forceinline__ void gemm_body(
    const float* __restrict__ A, const float* __restrict__ W,
    const float* __restrict__ bias, float* __restrict__ C, float outScale)
{
    __shared__ uint32_t As[128 * AS_STRIDE];
    __shared__ uint32_t Ws[32 * WS_STRIDE];

    const int tid = threadIdx.x;
    const int rowBase = blockIdx.x * 128;
    const int wid = tid >> 5;
    const int lane = tid & 31;
    const int g = lane >> 2;          // 0..7
    const int q = lane & 3;           // 0..3
    const int warpM = wid & 3;        // 0..3 -> 32-row slab
    const int warpN = wid >> 2;       // 0..1 -> 64-col slab

    float acc[2][8][4];
#pragma unroll
    for (int mt = 0; mt < 2; mt++)
#pragma unroll
        for (int nt = 0; nt < 8; nt++)
#pragma unroll
            for (int r = 0; r < 4; r++) acc[mt][nt][r] = 0.f;

    for (int kc = 0; kc < DD; kc += 32) {
        // A chunk [128][32] -> tf32 smem
#pragma unroll
        for (int it = 0; it < 4; it++) {
            int idx = tid + it * 256;   // 0..1023
            int r   = idx >> 3;         // 0..127
            int c4  = idx & 7;          // 0..7
            int grow = rowBase + r;
            float4 v = make_float4(0.f, 0.f, 0.f, 0.f);
            if (grow < NN) v = *(const float4*)(A + (size_t)grow * DD + kc + c4 * 4);
            if (BN) {
                int cb = kc + c4 * 4;
                v.x = fmaxf(v.x * g_scale[cb + 0] + g_shift[cb + 0], 0.f);
                v.y = fmaxf(v.y * g_scale[cb + 1] + g_shift[cb + 1], 0.f);
                v.z = fmaxf(v.z * g_scale[cb + 2] + g_shift[cb + 2], 0.f);
                v.w = fmaxf(v.w * g_scale[cb + 3] + g_shift[cb + 3], 0.f);
            }
            uint4 t = make_uint4(f2tf(v.x), f2tf(v.y), f2tf(v.z), f2tf(v.w));
            *(uint4*)&As[r * AS_STRIDE + c4 * 4] = t;
        }
        // W chunk [32][128] -> tf32 smem
#pragma unroll
        for (int it = 0; it < 4; it++) {
            int idx = tid + it * 256;
            int r   = idx >> 5;         // 0..31
            int c4  = idx & 31;         // 0..31
            float4 v = *(const float4*)(W + (size_t)(kc + r) * DD + c4 * 4);
            uint4 t = make_uint4(f2tf(v.x), f2tf(v.y), f2tf(v.z), f2tf(v.w));
            *(uint4*)&Ws[r * WS_STRIDE + c4 * 4] = t;
        }
        __syncthreads();

#pragma unroll
        for (int ks = 0; ks < 4; ks++) {
            const int k = ks * 8;
            uint32_t a[2][4];
#pragma unroll
            for (int mt = 0; mt < 2; mt++) {
                int Rm = warpM * 32 + mt * 16;
                a[mt][0] = As[(Rm + g)     * AS_STRIDE + k + q];
                a[mt][1] = As[(Rm + g + 8) * AS_STRIDE + k + q];
                a[mt][2] = As[(Rm + g)     * AS_STRIDE + k + q + 4];
                a[mt][3] = As[(Rm + g + 8) * AS_STRIDE + k + q + 4];
            }
            uint32_t b[8][2];
#pragma unroll
            for (int nt = 0; nt < 8; nt++) {
                int col = warpN * 64 + nt * 8 + g;
                b[nt][0] = Ws[(k + q)     * WS_STRIDE + col];
                b[nt][1] = Ws[(k + q + 4) * WS_STRIDE + col];
            }
#pragma unroll
            for (int mt = 0; mt < 2; mt++)
#pragma unroll
                for (int nt = 0; nt < 8; nt++)
                    mma_tf32(acc[mt][nt], a[mt], b[nt]);
        }
        __syncthreads();
    }

    // epilogue: bias + scale, float2 stores
#pragma unroll
    for (int nt = 0; nt < 8; nt++) {
        int col = warpN * 64 + nt * 8 + 2 * q;
        float bb0 = bias[col], bb1 = bias[col + 1];
#pragma unroll
        for (int mt = 0; mt < 2; mt++) {
            int r0 = rowBase + warpM * 32 + mt * 16 + g;
            if (r0 < NN) {
                float2 o = make_float2((acc[mt][nt][0] + bb0) * outScale,
                                       (acc[mt][nt][1] + bb1) * outScale);
                *(float2*)(C + (size_t)r0 * DD + col) = o;
            }
            int r1 = r0 + 8;
            if (r1 < NN) {
                float2 o = make_float2((acc[mt][nt][2] + bb0) * outScale,
                                       (acc[mt][nt][3] + bb1) * outScale);
                *(float2*)(C + (size_t)r1 * DD + col) = o;
            }
        }
    }
}

__global__ void __launch_bounds__(256, 2) k_gemm_proj(
    const float* __restrict__ x,
    const float* __restrict__ Wk, const float* __restrict__ bk,
    const float* __restrict__ Wm, const float* __restrict__ bm,
    const float* __restrict__ Wq, const float* __restrict__ bq)
{
    const float* W; const float* b; float* C; float sc = 1.f;
    if (blockIdx.y == 0)      { W = Wk; b = bk; C = g_K; }
    else if (blockIdx.y == 1) { W = Wm; b = bm; C = g_M; }
    else                      { W = Wq; b = bq; C = g_Q; sc = 0.17677669529663687f; } // 1/sqrt(32)
    gemm_body<false>(x, W, b, C, sc);
}

__global__ void __launch_bounds__(256, 2) k_gemm_mlp1(
    const float* __restrict__ W1, const float* __restrict__ b1)
{
    gemm_body<false>(g_out, W1, b1, g_h, 1.f);
}

__global__ void __launch_bounds__(256, 2) k_gemm_mlp2(
    const float* __restrict__ W2, const float* __restrict__ b2,
    float* __restrict__ outp)
{
    gemm_body<true>(g_h, W2, b2, outp, 1.f);
}

// =======================================================================
// pass 1 (CSR by src): warp per src node, Q cached, no atomics
// =======================================================================
__global__ void __launch_bounds__(256) k_edge_scores()
{
    int gwarp  = (blockIdx.x * blockDim.x + threadIdx.x) >> 5;
    int nwarps = (gridDim.x * blockDim.x) >> 5;
    int lane   = threadIdx.x & 31;
    for (int n = gwarp; n < NN; n += nwarps) {
        int beg = g_off_s[n];
        int end = g_off_s[n + 1];
        if (beg == end) continue;
        float4 q = *(const float4*)(g_Q + (size_t)n * DD + lane * 4);
        float ls = 0.f;
#pragma unroll 2
        for (int e = beg; e < end; e++) {
            int dst = g_csr_s_dst[e];
            float4 k = *(const float4*)(g_K + (size_t)dst * DD + lane * 4);
            float p = q.x * k.x + q.y * k.y + q.z * k.z + q.w * k.w;
            p += __shfl_xor_sync(0xffffffffu, p, 1);
            p += __shfl_xor_sync(0xffffffffu, p, 2);
            p += __shfl_xor_sync(0xffffffffu, p, 4);
            float ev = __expf(p);   // scores O(1): max-shift unnecessary
            if ((lane & 7) == 0) {
                int eid = g_csr_s_eid[e];
                g_ev[(size_t)eid * HH + (lane >> 3)] = ev;
                ls += ev;
            }
        }
        if ((lane & 7) == 0) {
            float deg = (float)(end - beg);
            g_rnorm[n * HH + (lane >> 3)] = deg / ls;
        }
    }
}

// =======================================================================
// pass 2 (CSR by dst): warp per dst node, register accumulate, one store
// =======================================================================
__global__ void __launch_bounds__(256) k_aggregate()
{
    int gwarp  = (blockIdx.x * blockDim.x + threadIdx.x) >> 5;
    int nwarps = (gridDim.x * blockDim.x) >> 5;
    int lane   = threadIdx.x & 31;
    int h      = lane >> 3;
    for (int n = gwarp; n < NN; n += nwarps) {
        int beg = g_off_d[n];
        int end = g_off_d[n + 1];
        float4 acc = make_float4(0.f, 0.f, 0.f, 0.f);
#pragma unroll 2
        for (int e = beg; e < end; e++) {
            int src = g_csr_d_src[e];
            int eid = g_csr_d_eid[e];
            float alpha = g_ev[(size_t)eid * HH + h] * g_rnorm[src * HH + h];
            float4 m = *(const float4*)(g_M + (size_t)src * DD + lane * 4);
            acc.x += m.x * alpha;
            acc.y += m.y * alpha;
            acc.z += m.z * alpha;
            acc.w += m.w * alpha;
        }
        *(float4*)(g_out + (size_t)n * DD + lane * 4) = acc;
    }
}

// =======================================================================
// BN stats over columns of g_h
// =======================================================================
__global__ void __launch_bounds__(128) k_colstats()
{
    int col = threadIdx.x;
    float s = 0.f, s2 = 0.f;
    for (int r = blockIdx.x; r < NN; r += gridDim.x) {
        float v = g_h[(size_t)r * DD + col];
        s += v; s2 += v * v;
    }
    atomicAdd(&g_colsum[col], s);
    atomicAdd(&g_colsumsq[col], s2);
}

__global__ void k_bnfinal(const float* __restrict__ gamma, const float* __restrict__ beta)
{
    int c = threadIdx.x;
    float invN = 1.0f / (float)NN;
    float mean = g_colsum[c] * invN;
    float var  = g_colsumsq[c] * invN - mean * mean;
    float rstd = rsqrtf(var + 1e-5f);
    float sc = rstd * gamma[c];
    g_scale[c] = sc;
    g_shift[c] = beta[c] - mean * sc;
}

// =======================================================================
// launcher
// =======================================================================
extern "C" void kernel_launch(void* const* d_in, const int* in_sizes, int n_in,
                              void* d_out, int out_size)
{
    const float* x     = (const float*)d_in[0];
    const void*  ei    = d_in[1];
    const float* Wk    = (const float*)d_in[2];
    const float* bk    = (const float*)d_in[3];
    const float* Wm    = (const float*)d_in[4];
    const float* bm    = (const float*)d_in[5];
    const float* Wq    = (const float*)d_in[6];
    const float* bq    = (const float*)d_in[7];
    const float* W1    = (const float*)d_in[8];
    const float* b1    = (const float*)d_in[9];
    const float* gamma = (const float*)d_in[10];
    const float* beta  = (const float*)d_in[11];
    const float* W2    = (const float*)d_in[12];
    const float* b2    = (const float*)d_in[13];
    float* out = (float*)d_out;

    // temp src/dst live in g_ev (written only later, in pass 1)
    int* srcTmp = (int*)g_ev;
    int* dstTmp = ((int*)g_ev) + EE;

    const int rowTiles = (NN + 127) / 128;  // 391

    k_detect<<<1, 256>>>((const unsigned long long*)ei);
    k_init<<<128, 256>>>();
    k_convert<<<512, 256>>>(ei, srcTmp, dstTmp);
    k_scanA<<<dim3(NB, 2), 1024>>>();
    k_scanB<<<1, 128>>>();
    k_scanC<<<dim3(NB, 2), 1024>>>();
    k_scatter<<<512, 256>>>(srcTmp, dstTmp);
    k_gemm_proj<<<dim3(rowTiles, 3), 256>>>(x, Wk, bk, Wm, bm, Wq, bq);
    k_edge_scores<<<2048, 256>>>();
    k_aggregate<<<2048, 256>>>();
    k_gemm_mlp1<<<rowTiles, 256>>>(W1, b1);
    k_colstats<<<512, 128>>>();
    k_bnfinal<<<1, 128>>>(gamma, beta);
    k_gemm_mlp2<<<rowTiles, 256>>>(W2, b2, out);
}